// round 14
// baseline (speedup 1.0000x reference)
#include <cuda_runtime.h>
#include <cuda_fp16.h>
#include <math.h>
#include <cstdint>

#define BSZ  16      // batch
#define NCAP 1152    // primary caps
#define DP   8       // dim primary
#define DDIG 10      // digit caps
#define DD   16      // dim digit
#define JP   (DD/2)  // half2 pairs per row = 8

#define TILE_N 16
#define NT (NCAP / TILE_N)   // 72

#define K2CH 9               // k2 chunks per b
#define K2N (NCAP / K2CH)    // 128

// Scratch (device globals; fully overwritten every call)
__device__ __align__(16) __half2 g_Uh[BSZ * DDIG * NCAP * JP];  // U_hat fp16 (5.9 MB)
__device__ __align__(16) float g_Tp[BSZ * DDIG * DD * NT];      // T tile partials (fp32)
__device__ __align__(16) float g_wgt[BSZ * DDIG * NCAP];        // weights [b][d][n]

// -------------------------------------------------------------------------
// K1: votes. 256 threads: t = (bh, nl, jp); each thread does 8 batches.
// Stores half2 (128B contiguous per warp), fp32 T tile-partials, no atomics.
// Grid (DDIG, NT) = 720 CTAs x 256 threads.
// -------------------------------------------------------------------------
__global__ __launch_bounds__(256) void k1_votes(
    const float* __restrict__ u,   // [B][N][DP]
    const float* __restrict__ W)   // [D][N][DD][DP]
{
    const int d    = blockIdx.x;
    const int tile = blockIdx.y;
    const int n0   = tile * TILE_N;
    const int t    = threadIdx.x;
    const int bh   = t >> 7;          // 0..1 (batch half)
    const int rem  = t & 127;
    const int jp   = rem & 7;
    const int nl   = rem >> 3;
    const int n    = n0 + nl;
    const int lane = t & 31;
    const int w    = t >> 5;          // 0..7; bh = w>>2
    const int wq   = w & 3;

    // W rows j=2jp, 2jp+1: 64 B contiguous (bh pair dedups in L1)
    const float4* wp = reinterpret_cast<const float4*>(
        W + ((size_t)(d * NCAP + n) * DD + 2 * jp) * DP);
    const float4 w0 = wp[0];
    const float4 w1 = wp[1];
    const float4 w2 = wp[2];
    const float4 w3 = wp[3];

    __shared__ __align__(16) float us[BSZ][TILE_N][DP];   // 8 KB
    __shared__ float2 red[2][4][8][JP];                   // 4 KB [bh][wq][bi][jp]

    // stage u tile: 512 float4, 2 per thread
    #pragma unroll
    for (int it = 0; it < 2; ++it) {
        const int idx = it * 256 + t;
        const int b   = idx >> 5;
        const int rm  = idx & 31;
        const float4 v = reinterpret_cast<const float4*>(
            u + (size_t)b * NCAP * DP + (size_t)n0 * DP)[rm];
        reinterpret_cast<float4*>(&us[b][0][0])[rm] = v;
    }
    __syncthreads();

    #pragma unroll
    for (int bi = 0; bi < 8; ++bi) {
        const int b = bh * 8 + bi;
        const float4* up = reinterpret_cast<const float4*>(&us[b][nl][0]);
        const float4 u0 = up[0];
        const float4 u1 = up[1];
        const float accE = w0.x * u0.x + w0.y * u0.y + w0.z * u0.z + w0.w * u0.w
                         + w1.x * u1.x + w1.y * u1.y + w1.z * u1.z + w1.w * u1.w;
        const float accO = w2.x * u0.x + w2.y * u0.y + w2.z * u0.z + w2.w * u0.w
                         + w3.x * u1.x + w3.y * u1.y + w3.z * u1.z + w3.w * u1.w;

        g_Uh[((size_t)(b * DDIG + d) * NCAP + n) * JP + jp] =
            __floats2half2_rn(accE, accO);

        // T partial over nl (4 nl per warp): xor8 + xor16
        float pe = accE, po = accO;
        pe += __shfl_xor_sync(0xffffffffu, pe, 8);
        pe += __shfl_xor_sync(0xffffffffu, pe, 16);
        po += __shfl_xor_sync(0xffffffffu, po, 8);
        po += __shfl_xor_sync(0xffffffffu, po, 16);
        if (lane < 8) red[bh][wq][bi][lane] = make_float2(pe, po);
    }
    __syncthreads();

    // 256 (b,j) outputs over 256 threads: 1 each
    {
        const int b2  = t >> 4;
        const int j2  = t & 15;
        const int jp2 = j2 >> 1;
        const int bh2 = b2 >> 3;
        const int bi2 = b2 & 7;
        float s = 0.f;
        #pragma unroll
        for (int ww = 0; ww < 4; ++ww) {
            const float2 v = red[bh2][ww][bi2][jp2];
            s += (j2 & 1) ? v.y : v.x;
        }
        g_Tp[((size_t)(b2 * DDIG + d) * DD + j2) * NT + tile] = s;
    }
}

// -------------------------------------------------------------------------
// K2: streaming softmax weights. Grid (BSZ, 9) x 128 threads; thread = one n.
// High MLP: 20 independent LDG.128 over the 10 d rows (half2 data).
// -------------------------------------------------------------------------
__global__ __launch_bounds__(128) void k2_wgt(
    const float* __restrict__ Bp)   // [D][1][N]
{
    const int b  = blockIdx.x;
    const int ch = blockIdx.y;
    const int t  = threadIdx.x;

    __shared__ float Tsm[DDIG][DD];

    // T[b,d,j] from 72 contiguous tile partials (18 f4 per (d,j))
    for (int idx = t; idx < DDIG * DD; idx += 128) {
        const float4* p = reinterpret_cast<const float4*>(
            &g_Tp[(size_t)(b * DDIG * DD + idx) * NT]);
        float s = 0.f;
        #pragma unroll
        for (int k = 0; k < NT / 4; ++k) {
            const float4 v = p[k];
            s += v.x + v.y + v.z + v.w;
        }
        Tsm[idx >> 4][idx & 15] = s;
    }
    __syncthreads();

    const int n = ch * K2N + t;
    const float inv_sqrt8 = 0.3535533905932738f;

    float a[DDIG];
    #pragma unroll
    for (int d = 0; d < DDIG; ++d) {
        const uint4* r = reinterpret_cast<const uint4*>(
            g_Uh + ((size_t)(b * DDIG + d) * NCAP + n) * JP);
        const uint4 A = r[0];
        const uint4 B = r[1];
        const float* T = Tsm[d];
        float s = 0.f;
        {
            const float2 f0 = __half22float2(*reinterpret_cast<const __half2*>(&A.x));
            const float2 f1 = __half22float2(*reinterpret_cast<const __half2*>(&A.y));
            const float2 f2 = __half22float2(*reinterpret_cast<const __half2*>(&A.z));
            const float2 f3 = __half22float2(*reinterpret_cast<const __half2*>(&A.w));
            s += T[0] * f0.x + T[1] * f0.y + T[2] * f1.x + T[3] * f1.y
               + T[4] * f2.x + T[5] * f2.y + T[6] * f3.x + T[7] * f3.y;
        }
        {
            const float2 f0 = __half22float2(*reinterpret_cast<const __half2*>(&B.x));
            const float2 f1 = __half22float2(*reinterpret_cast<const __half2*>(&B.y));
            const float2 f2 = __half22float2(*reinterpret_cast<const __half2*>(&B.z));
            const float2 f3 = __half22float2(*reinterpret_cast<const __half2*>(&B.w));
            s += T[8]  * f0.x + T[9]  * f0.y + T[10] * f1.x + T[11] * f1.y
               + T[12] * f2.x + T[13] * f2.y + T[14] * f3.x + T[15] * f3.y;
        }
        a[d] = s * inv_sqrt8;
    }

    float m = a[0];
    #pragma unroll
    for (int d = 1; d < DDIG; ++d) m = fmaxf(m, a[d]);
    float e[DDIG], denom = 0.f;
    #pragma unroll
    for (int d = 0; d < DDIG; ++d) { e[d] = __expf(a[d] - m); denom += e[d]; }
    const float rden = 1.f / denom;

    #pragma unroll
    for (int d = 0; d < DDIG; ++d)
        g_wgt[((size_t)(b * DDIG + d)) * NCAP + n] =
            e[d] * rden + __ldg(&Bp[(size_t)d * NCAP + n]);
}

// -------------------------------------------------------------------------
// K3: S[b,d,:] = sum_n wgt[b,d,n] * U[b,d,n,:]; inline squash.
// Grid (160) x 512 threads; thread=(jp 0..7, ng 0..63). Coalesced half2.
// No atomics, no fences — each CTA owns its (b,d) end-to-end.
// -------------------------------------------------------------------------
__global__ __launch_bounds__(512) void k3_out(float* __restrict__ out)
{
    const int bd   = blockIdx.x;      // b*DDIG + d
    const int t    = threadIdx.x;
    const int jp   = t & 7;
    const int ng   = t >> 3;          // 0..63
    const int lane = t & 31;
    const int w    = t >> 5;          // 0..15

    __shared__ float wgs[NCAP];       // 4.6 KB
    __shared__ float2 red[16][JP];    // 1 KB
    __shared__ float Ssm[DD];
    __shared__ float coef_sh;

    const float* wg = g_wgt + (size_t)bd * NCAP;
    for (int idx = t; idx < NCAP / 4; idx += 512)
        reinterpret_cast<float4*>(wgs)[idx] =
            reinterpret_cast<const float4*>(wg)[idx];
    __syncthreads();

    const __half2* Ub = g_Uh + (size_t)bd * NCAP * JP;

    float2 acc = make_float2(0.f, 0.f);
    #pragma unroll
    for (int k = 0; k < NCAP / 64; ++k) {     // 18 iters, independent loads
        const int n = k * 64 + ng;
        const float2 f = __half22float2(Ub[(size_t)n * JP + jp]);
        const float wv = wgs[n];
        acc.x += wv * f.x;
        acc.y += wv * f.y;
    }

    // reduce over ng-within-warp (lane>>3): xor8 + xor16
    acc.x += __shfl_xor_sync(0xffffffffu, acc.x, 8);
    acc.x += __shfl_xor_sync(0xffffffffu, acc.x, 16);
    acc.y += __shfl_xor_sync(0xffffffffu, acc.y, 8);
    acc.y += __shfl_xor_sync(0xffffffffu, acc.y, 16);
    if (lane < 8) red[w][lane] = acc;
    __syncthreads();

    if (t < JP) {
        float sx = 0.f, sy = 0.f;
        #pragma unroll
        for (int ww = 0; ww < 16; ++ww) {
            const float2 v = red[ww][t];
            sx += v.x; sy += v.y;
        }
        Ssm[2 * t]     = sx;
        Ssm[2 * t + 1] = sy;
    }
    __syncthreads();
    if (t == 0) {
        float nn = 0.f;
        #pragma unroll
        for (int jj = 0; jj < DD; ++jj) nn += Ssm[jj] * Ssm[jj];
        const float norm = sqrtf(nn);
        const float EPS  = 1e-7f;
        coef_sh = (1.f - 1.f / (__expf(norm) + EPS)) / (norm + EPS);
    }
    __syncthreads();
    if (t < DD)
        out[(size_t)bd * DD + t] = coef_sh * Ssm[t];
}

// -------------------------------------------------------------------------
extern "C" void kernel_launch(void* const* d_in, const int* in_sizes, int n_in,
                              void* d_out, int out_size)
{
    const float* u  = (const float*)d_in[0];   // primary_caps [16,1152,8]
    const float* W  = (const float*)d_in[1];   // W            [10,1152,16,8]
    const float* Bp = (const float*)d_in[2];   // B_prior      [10,1,1152]
    float* out      = (float*)d_out;           // [16,10,16]

    (void)in_sizes; (void)n_in; (void)out_size;

    k1_votes<<<dim3(DDIG, NT), 256>>>(u, W);
    k2_wgt  <<<dim3(BSZ, K2CH), 128>>>(Bp);
    k3_out  <<<BSZ * DDIG, 512>>>(out);
}